// round 3
// baseline (speedup 1.0000x reference)
#include <cuda_runtime.h>
#include <stdint.h>

// ---------------------------------------------------------------------------
// Valid (i, ph) combos per axis: i2 = i + 2*ph - 14 in [0,7). 25 combos,
// 625 features total. Ordered i-major, ph ascending.
// ---------------------------------------------------------------------------
__constant__ int c_I [25] = {0,0,0,0, 1,1,1, 2,2,2,2, 3,3,3, 4,4,4,4, 5,5,5, 6,6,6,6};
__constant__ int c_PH[25] = {7,8,9,10, 7,8,9, 6,7,8,9, 6,7,8, 5,6,7,8, 5,6,7, 4,5,6,7};
__constant__ int c_I2[25] = {0,2,4,6, 1,3,5, 0,2,4,6, 1,3,5, 0,2,4,6, 1,3,5, 0,2,4,6};

static const int B_  = 1024;
static const int KC_ = 640;            // 625 valid features padded to 640
__device__ float g_X  [B_ * KC_];      // compact correlation features [B][640]
__device__ float g_W1g[1024 * KC_];    // gathered W1 columns, [n][640]
__device__ float g_H1 [B_ * 1024];
__device__ float g_H2 [B_ * 1024];

// ---------------------------------------------------------------------------
// Correlation v2: one CTA per RoI. Patches stored TRANSPOSED in SMEM as
// [pix][c] with row stride 260 floats (16B-aligned rows, 8-bank spread).
// 625 threads each do a length-256 dot as 64 float4 LDS.128 pairs.
// ---------------------------------------------------------------------------
#define CORR_STRIDE 260

__global__ __launch_bounds__(640) void corr_kernel(
    const float* __restrict__ p1, const float* __restrict__ p2,
    float* __restrict__ X)
{
    extern __shared__ float sm[];
    float* s1 = sm;                      // [49][260]
    float* s2 = sm + 49 * CORR_STRIDE;   // [49][260]

    const int b = blockIdx.x;
    const int t = threadIdx.x;
    const float* g1 = p1 + b * 12544;
    const float* g2 = p2 + b * 12544;

    for (int idx = t; idx < 12544; idx += 640) {
        int c   = idx / 49;
        int pix = idx - c * 49;
        s1[pix * CORR_STRIDE + c] = g1[idx];
        s2[pix * CORR_STRIDE + c] = g2[idx];
    }
    __syncthreads();

    if (t < 625) {
        int u = t / 25;
        int v = t - u * 25;
        int pA = c_I [u] * 7 + c_I [v];
        int pB = c_I2[u] * 7 + c_I2[v];
        const float4* a  = (const float4*)(s1 + pA * CORR_STRIDE);
        const float4* bb = (const float4*)(s2 + pB * CORR_STRIDE);
        float acc = 0.f;
        #pragma unroll 8
        for (int i = 0; i < 64; i++) {
            float4 av = a[i];
            float4 bv = bb[i];
            acc = fmaf(av.x, bv.x, acc);
            acc = fmaf(av.y, bv.y, acc);
            acc = fmaf(av.z, bv.z, acc);
            acc = fmaf(av.w, bv.w, acc);
        }
        X[b * KC_ + t] = acc;
    } else {
        X[b * KC_ + t] = 0.f;
    }
}

// ---------------------------------------------------------------------------
// Gather the 625 used W1 columns into [n][640] with zero padding.
// ---------------------------------------------------------------------------
__global__ __launch_bounds__(640) void gather_w1_kernel(
    const float* __restrict__ W1, float* __restrict__ W1g)
{
    const int n = blockIdx.x;
    const int k = threadIdx.x;
    float v_out = 0.f;
    if (k < 625) {
        int u = k / 25;
        int v = k - u * 25;
        int feat = (c_PH[u] * 16 + c_PH[v]) * 49 + c_I[u] * 7 + c_I[v];
        v_out = W1[n * 12544 + feat];
    }
    W1g[n * KC_ + k] = v_out;
}

// ---------------------------------------------------------------------------
// fp32 SIMT GEMM v2: C[M,N] = A[M,K] * Bt[N,K]^T + bias (+relu).
// Tile 128(m) x 64(n), BK=16, 128 threads, 8x8 register microtiles,
// register-prefetch software pipeline (LDG next chunk during compute).
// ---------------------------------------------------------------------------
template<int RELU>
__global__ __launch_bounds__(128, 4) void gemm_bias_kernel(
    const float* __restrict__ A, const float* __restrict__ Bt,
    const float* __restrict__ bias, float* __restrict__ C,
    int M, int N, int K)
{
    __shared__ float As[16][132];   // [k][m], 132 stride: conflict-free
    __shared__ float Bs[16][68];    // [k][n]

    const int tid = threadIdx.x;
    const int m0 = blockIdx.y * 128;
    const int n0 = blockIdx.x * 64;
    const int tm = tid >> 3;        // 0..15  -> rows tm*8 .. tm*8+7
    const int tn = tid & 7;         // 0..7   -> cols tn*8 .. tn*8+7

    // A loader: thread t owns row m0+t, loads 16 floats (4 x float4)
    const float* Aptr = A + (size_t)(m0 + tid) * K;
    // B loader: thread t owns (n = t>>1, k-half = (t&1)*8), 2 x float4
    const int bn = tid >> 1;
    const int bk = (tid & 1) * 8;
    const float* Bptr = Bt + (size_t)(n0 + bn) * K + bk;

    float4 ar[4], br[2];
    #pragma unroll
    for (int q = 0; q < 4; q++) ar[q] = *(const float4*)(Aptr + q * 4);
    br[0] = *(const float4*)(Bptr);
    br[1] = *(const float4*)(Bptr + 4);

    float acc[8][8];
    #pragma unroll
    for (int i = 0; i < 8; i++)
        #pragma unroll
        for (int j = 0; j < 8; j++) acc[i][j] = 0.f;

    const int nch = K >> 4;
    for (int ch = 0; ch < nch; ch++) {
        // stage regs -> smem
        #pragma unroll
        for (int q = 0; q < 4; q++) {
            As[q * 4 + 0][tid] = ar[q].x;
            As[q * 4 + 1][tid] = ar[q].y;
            As[q * 4 + 2][tid] = ar[q].z;
            As[q * 4 + 3][tid] = ar[q].w;
        }
        Bs[bk + 0][bn] = br[0].x;
        Bs[bk + 1][bn] = br[0].y;
        Bs[bk + 2][bn] = br[0].z;
        Bs[bk + 3][bn] = br[0].w;
        Bs[bk + 4][bn] = br[1].x;
        Bs[bk + 5][bn] = br[1].y;
        Bs[bk + 6][bn] = br[1].z;
        Bs[bk + 7][bn] = br[1].w;
        __syncthreads();

        // prefetch next chunk while computing this one
        if (ch + 1 < nch) {
            const float* Ap = Aptr + (ch + 1) * 16;
            #pragma unroll
            for (int q = 0; q < 4; q++) ar[q] = *(const float4*)(Ap + q * 4);
            const float* Bp = Bptr + (ch + 1) * 16;
            br[0] = *(const float4*)(Bp);
            br[1] = *(const float4*)(Bp + 4);
        }

        #pragma unroll
        for (int k = 0; k < 16; k++) {
            float4 a0 = *(const float4*)&As[k][tm * 8];
            float4 a1 = *(const float4*)&As[k][tm * 8 + 4];
            float4 b0 = *(const float4*)&Bs[k][tn * 8];
            float4 b1 = *(const float4*)&Bs[k][tn * 8 + 4];
            float a[8] = {a0.x, a0.y, a0.z, a0.w, a1.x, a1.y, a1.z, a1.w};
            float bb[8] = {b0.x, b0.y, b0.z, b0.w, b1.x, b1.y, b1.z, b1.w};
            #pragma unroll
            for (int i = 0; i < 8; i++)
                #pragma unroll
                for (int j = 0; j < 8; j++)
                    acc[i][j] = fmaf(a[i], bb[j], acc[i][j]);
        }
        __syncthreads();
    }

    // epilogue
    float4 bz0 = *(const float4*)&bias[n0 + tn * 8];
    float4 bz1 = *(const float4*)&bias[n0 + tn * 8 + 4];
    #pragma unroll
    for (int i = 0; i < 8; i++) {
        float4 o0, o1;
        o0.x = acc[i][0] + bz0.x; o0.y = acc[i][1] + bz0.y;
        o0.z = acc[i][2] + bz0.z; o0.w = acc[i][3] + bz0.w;
        o1.x = acc[i][4] + bz1.x; o1.y = acc[i][5] + bz1.y;
        o1.z = acc[i][6] + bz1.z; o1.w = acc[i][7] + bz1.w;
        if (RELU) {
            o0.x = fmaxf(o0.x, 0.f); o0.y = fmaxf(o0.y, 0.f);
            o0.z = fmaxf(o0.z, 0.f); o0.w = fmaxf(o0.w, 0.f);
            o1.x = fmaxf(o1.x, 0.f); o1.y = fmaxf(o1.y, 0.f);
            o1.z = fmaxf(o1.z, 0.f); o1.w = fmaxf(o1.w, 0.f);
        }
        float* crow = C + (size_t)(m0 + tm * 8 + i) * N + n0 + tn * 8;
        *(float4*)(crow)     = o0;
        *(float4*)(crow + 4) = o1;
    }
}

// ---------------------------------------------------------------------------
// FC3: out[b][o] = H2[b] . W3[o] + b3[o]. One warp per (b, o).
// ---------------------------------------------------------------------------
__global__ __launch_bounds__(128) void fc3_kernel(
    const float* __restrict__ H2, const float* __restrict__ W3,
    const float* __restrict__ b3, float* __restrict__ out)
{
    const int b = blockIdx.x;
    const int o = threadIdx.x >> 5;
    const int l = threadIdx.x & 31;
    const float4* h = (const float4*)(H2 + b * 1024);
    const float4* w = (const float4*)(W3 + o * 1024);
    float s = 0.f;
    #pragma unroll
    for (int i = 0; i < 8; i++) {
        float4 hv = h[i * 32 + l];
        float4 wv = w[i * 32 + l];
        s = fmaf(hv.x, wv.x, s);
        s = fmaf(hv.y, wv.y, s);
        s = fmaf(hv.z, wv.z, s);
        s = fmaf(hv.w, wv.w, s);
    }
    #pragma unroll
    for (int off = 16; off; off >>= 1)
        s += __shfl_xor_sync(0xFFFFFFFFu, s, off);
    if (l == 0) out[b * 4 + o] = s + b3[o];
}

// ---------------------------------------------------------------------------
extern "C" void kernel_launch(void* const* d_in, const int* in_sizes, int n_in,
                              void* d_out, int out_size)
{
    (void)in_sizes; (void)n_in; (void)out_size;
    const float* p1 = (const float*)d_in[0];
    const float* p2 = (const float*)d_in[1];
    const float* W1 = (const float*)d_in[2];
    const float* b1 = (const float*)d_in[3];
    const float* W2 = (const float*)d_in[4];
    const float* b2 = (const float*)d_in[5];
    const float* W3 = (const float*)d_in[6];
    const float* b3 = (const float*)d_in[7];
    float* out = (float*)d_out;

    float *X, *W1g, *H1, *H2;
    cudaGetSymbolAddress((void**)&X,   g_X);
    cudaGetSymbolAddress((void**)&W1g, g_W1g);
    cudaGetSymbolAddress((void**)&H1,  g_H1);
    cudaGetSymbolAddress((void**)&H2,  g_H2);

    const int corr_smem = 2 * 49 * CORR_STRIDE * (int)sizeof(float); // 101,920 B
    cudaFuncSetAttribute(corr_kernel,
                         cudaFuncAttributeMaxDynamicSharedMemorySize, corr_smem);

    corr_kernel<<<1024, 640, corr_smem>>>(p1, p2, X);
    gather_w1_kernel<<<1024, 640>>>(W1, W1g);

    dim3 grid(16, 8);   // N/64, M/128
    gemm_bias_kernel<1><<<grid, 128>>>(X,  W1g, b1, H1, 1024, 1024, 640);
    gemm_bias_kernel<1><<<grid, 128>>>(H1, W2,  b2, H2, 1024, 1024, 1024);
    fc3_kernel<<<1024, 128>>>(H2, W3, b3, out);
}

// round 5
// speedup vs baseline: 1.4753x; 1.4753x over previous
#include <cuda_runtime.h>
#include <cuda_bf16.h>
#include <stdint.h>

// ===========================================================================
// Helpers (baseline PTX only — no sm_100a-gated instructions)
// ===========================================================================
__device__ __forceinline__ uint32_t smem_u32(const void* p) {
    uint32_t a;
    asm("{ .reg .u64 t; cvta.to.shared.u64 t, %1; cvt.u32.u64 %0, t; }"
        : "=r"(a) : "l"(p));
    return a;
}
#define CP_COMMIT() asm volatile("cp.async.commit_group;" ::: "memory")
#define CP_WAIT2()  asm volatile("cp.async.wait_group 2;" ::: "memory")
__device__ __forceinline__ void cp16(uint32_t saddr, const void* g) {
    asm volatile("cp.async.cg.shared.global [%0], [%1], 16;" :: "r"(saddr), "l"(g));
}
__device__ __forceinline__ void ldm_x4(uint32_t& r0, uint32_t& r1,
                                       uint32_t& r2, uint32_t& r3, uint32_t a) {
    asm volatile("ldmatrix.sync.aligned.m8n8.x4.shared.b16 {%0,%1,%2,%3}, [%4];"
                 : "=r"(r0), "=r"(r1), "=r"(r2), "=r"(r3) : "r"(a));
}
__device__ __forceinline__ void hmma(float& d0, float& d1, float& d2, float& d3,
                                     uint32_t a0, uint32_t a1, uint32_t a2, uint32_t a3,
                                     uint32_t b0, uint32_t b1) {
    asm volatile("mma.sync.aligned.m16n8k16.row.col.f32.bf16.bf16.f32 "
                 "{%0,%1,%2,%3},{%4,%5,%6,%7},{%8,%9},{%0,%1,%2,%3};"
                 : "+f"(d0), "+f"(d1), "+f"(d2), "+f"(d3)
                 : "r"(a0), "r"(a1), "r"(a2), "r"(a3), "r"(b0), "r"(b1));
}
__device__ __forceinline__ uint32_t sw128(uint32_t off) {
    return off ^ ((off >> 3) & 0x70);
}

// ===========================================================================
// Valid (i, ph) combos per axis: 25 combos -> 625 of 12544 features nonzero.
// ===========================================================================
__constant__ int c_I [25] = {0,0,0,0, 1,1,1, 2,2,2,2, 3,3,3, 4,4,4,4, 5,5,5, 6,6,6,6};
__constant__ int c_PH[25] = {7,8,9,10, 7,8,9, 6,7,8,9, 6,7,8, 5,6,7,8, 5,6,7, 4,5,6,7};
__constant__ int c_I2[25] = {0,2,4,6, 1,3,5, 0,2,4,6, 1,3,5, 0,2,4,6, 1,3,5, 0,2,4,6};

static const int B_  = 1024;
static const int KC_ = 640;
__device__ __nv_bfloat16 g_Xh [B_ * KC_];
__device__ __nv_bfloat16 g_Xl [B_ * KC_];
__device__ __nv_bfloat16 g_W1h[1024 * KC_];
__device__ __nv_bfloat16 g_W1l[1024 * KC_];
__device__ __nv_bfloat16 g_W2h[1024 * 1024];
__device__ __nv_bfloat16 g_W2l[1024 * 1024];
__device__ __nv_bfloat16 g_H1h[B_ * 1024];
__device__ __nv_bfloat16 g_H1l[B_ * 1024];
__device__ float         g_H2 [B_ * 1024];

__device__ __forceinline__ void split_bf16(float x, __nv_bfloat16& h, __nv_bfloat16& l) {
    h = __float2bfloat16(x);
    l = __float2bfloat16(x - __bfloat162float(h));
}

// ===========================================================================
// Correlation: one CTA per RoI; transposed SMEM [pix][c] stride 260.
// Emits hi/lo bf16 features (padded to 640).
// ===========================================================================
#define CORR_STRIDE 260
__global__ __launch_bounds__(640) void corr_kernel(
    const float* __restrict__ p1, const float* __restrict__ p2,
    __nv_bfloat16* __restrict__ Xh, __nv_bfloat16* __restrict__ Xl)
{
    extern __shared__ float sm[];
    float* s1 = sm;
    float* s2 = sm + 49 * CORR_STRIDE;
    const int b = blockIdx.x;
    const int t = threadIdx.x;
    const float* g1 = p1 + b * 12544;
    const float* g2 = p2 + b * 12544;
    for (int idx = t; idx < 12544; idx += 640) {
        int c = idx / 49, pix = idx - c * 49;
        s1[pix * CORR_STRIDE + c] = g1[idx];
        s2[pix * CORR_STRIDE + c] = g2[idx];
    }
    __syncthreads();
    if (t < 625) {
        int u = t / 25, v = t - u * 25;
        const float4* a  = (const float4*)(s1 + (c_I [u] * 7 + c_I [v]) * CORR_STRIDE);
        const float4* bb = (const float4*)(s2 + (c_I2[u] * 7 + c_I2[v]) * CORR_STRIDE);
        float acc = 0.f;
        #pragma unroll 8
        for (int i = 0; i < 64; i++) {
            float4 av = a[i], bv = bb[i];
            acc = fmaf(av.x, bv.x, acc); acc = fmaf(av.y, bv.y, acc);
            acc = fmaf(av.z, bv.z, acc); acc = fmaf(av.w, bv.w, acc);
        }
        __nv_bfloat16 h, l; split_bf16(acc, h, l);
        Xh[b * KC_ + t] = h; Xl[b * KC_ + t] = l;
    } else {
        Xh[b * KC_ + t] = __float2bfloat16(0.f);
        Xl[b * KC_ + t] = __float2bfloat16(0.f);
    }
}

// ===========================================================================
// Gather the 625 used W1 columns -> hi/lo bf16 [n][640]
// ===========================================================================
__global__ __launch_bounds__(640) void gather_w1_kernel(
    const float* __restrict__ W1,
    __nv_bfloat16* __restrict__ Wh, __nv_bfloat16* __restrict__ Wl)
{
    const int n = blockIdx.x, k = threadIdx.x;
    float v_out = 0.f;
    if (k < 625) {
        int u = k / 25, v = k - u * 25;
        int feat = (c_PH[u] * 16 + c_PH[v]) * 49 + c_I[u] * 7 + c_I[v];
        v_out = W1[n * 12544 + feat];
    }
    __nv_bfloat16 h, l; split_bf16(v_out, h, l);
    Wh[n * KC_ + k] = h; Wl[n * KC_ + k] = l;
}

// ===========================================================================
// Split W2 fp32 -> hi/lo bf16
// ===========================================================================
__global__ __launch_bounds__(256) void split_w2_kernel(
    const float* __restrict__ W2,
    __nv_bfloat16* __restrict__ Wh, __nv_bfloat16* __restrict__ Wl)
{
    const int row = blockIdx.x;
    const int t = threadIdx.x;
    float4 v = *(const float4*)(W2 + row * 1024 + t * 4);
    __nv_bfloat16 h0,l0,h1,l1,h2,l2,h3,l3;
    split_bf16(v.x, h0, l0); split_bf16(v.y, h1, l1);
    split_bf16(v.z, h2, l2); split_bf16(v.w, h3, l3);
    __nv_bfloat162* ph = (__nv_bfloat162*)(Wh + row * 1024 + t * 4);
    __nv_bfloat162* pl = (__nv_bfloat162*)(Wl + row * 1024 + t * 4);
    ph[0] = __nv_bfloat162(h0, h1); ph[1] = __nv_bfloat162(h2, h3);
    pl[0] = __nv_bfloat162(l0, l1); pl[1] = __nv_bfloat162(l2, l3);
}

// ===========================================================================
// HMMA bf16-split GEMM: C = relu(A * Bt^T + bias)
// Virtual K' = 3K streamed as chunks: [Ah|Al|Ah] x [Bh|Bh|Bl].
// CTA tile 128(m) x 64(n), BK=64 (128B rows, SW128), 3-stage cp.async,
// 8 warps in 4(m) x 2(n), warp tile 32x32, mma.sync m16n8k16 bf16.
// OUT_BF16=1: emit hi/lo bf16 (for next layer); 0: emit fp32.
// ===========================================================================
#define NS 3
#define STAGE_BYTES (128 * 128 + 64 * 128)   // A 16KB + B 8KB = 24KB

template<int OUT_BF16>
__global__ __launch_bounds__(256, 2) void hmma_fc_kernel(
    const __nv_bfloat16* __restrict__ Ah, const __nv_bfloat16* __restrict__ Al,
    const __nv_bfloat16* __restrict__ Bh, const __nv_bfloat16* __restrict__ Bl,
    const float* __restrict__ bias,
    float* __restrict__ Cf, __nv_bfloat16* __restrict__ Ch,
    __nv_bfloat16* __restrict__ Cl, int K)
{
    extern __shared__ char smem[];
    const uint32_t sbase = smem_u32(smem);

    const int tid  = threadIdx.x;
    const int lane = tid & 31;
    const int wid  = tid >> 5;
    const int wm   = wid & 3;      // m warp: 0..3 -> rows wm*32
    const int wn   = wid >> 2;     // n warp: 0..1 -> cols wn*32
    const int m0 = blockIdx.y * 128, n0 = blockIdx.x * 64;

    const int cpt = K >> 6;        // 64-elem chunks per term
    const int nch = 3 * cpt;
    const size_t krow = (size_t)K * 2;

    auto fill = [&](int chunk, int stage) {
        int term = (chunk >= 2 * cpt) ? 2 : (chunk >= cpt ? 1 : 0);
        int cc = chunk - term * cpt;
        const __nv_bfloat16* As = (term == 1) ? Al : Ah;
        const __nv_bfloat16* Bs = (term == 2) ? Bl : Bh;
        const char* ag = (const char*)As + (size_t)m0 * krow + cc * 128;
        const char* bg = (const char*)Bs + (size_t)n0 * krow + cc * 128;
        uint32_t da = sbase + stage * STAGE_BYTES;
        uint32_t db = da + 128 * 128;
        #pragma unroll
        for (int q = 0; q < 4; q++) {           // A: 1024 16B chunks / 256 thr
            int i = tid + q * 256;
            int row = i >> 3, c = (i & 7) << 4;
            cp16(da + sw128((uint32_t)(row << 7) + c), ag + (size_t)row * krow + c);
        }
        #pragma unroll
        for (int q = 0; q < 2; q++) {           // B: 512 chunks
            int i = tid + q * 256;
            int row = i >> 3, c = (i & 7) << 4;
            cp16(db + sw128((uint32_t)(row << 7) + c), bg + (size_t)row * krow + c);
        }
    };

    float acc[2][4][4];
    #pragma unroll
    for (int mt = 0; mt < 2; mt++)
        #pragma unroll
        for (int nt = 0; nt < 4; nt++)
            #pragma unroll
            for (int q = 0; q < 4; q++) acc[mt][nt][q] = 0.f;

    fill(0, 0); CP_COMMIT();
    fill(1, 1); CP_COMMIT();

    // Per-lane ldmatrix address components (row part is fixed per lane).
    const int arow_base = wm * 32 + (lane & 15);           // + mt*16
    const int acol_half = ((lane >> 4) & 1) << 4;          // k-half byte
    const int brow_base = wn * 32 + (lane & 7) + ((lane >> 4) << 3);  // + ntp*16
    const int bcol_half = (((lane >> 3) & 1)) << 4;

    for (int ch = 0; ch < nch; ch++) {
        if (ch + 2 < nch) fill(ch + 2, (ch + 2) % NS);
        CP_COMMIT();
        CP_WAIT2();
        __syncthreads();

        const uint32_t sa = sbase + (ch % NS) * STAGE_BYTES;
        const uint32_t sb = sa + 128 * 128;

        #pragma unroll
        for (int ks = 0; ks < 4; ks++) {
            uint32_t a[2][4], b[2][4];
            #pragma unroll
            for (int mt = 0; mt < 2; mt++) {
                int row = arow_base + mt * 16;
                uint32_t off = (uint32_t)(row << 7) + (ks * 32 + acol_half);
                ldm_x4(a[mt][0], a[mt][1], a[mt][2], a[mt][3],
                       sa + (off ^ (((uint32_t)row & 7) << 4)));
            }
            #pragma unroll
            for (int np = 0; np < 2; np++) {   // n-tile pairs (0,1) and (2,3)
                int row = brow_base + np * 16;
                uint32_t off = (uint32_t)(row << 7) + (ks * 32 + bcol_half);
                ldm_x4(b[np][0], b[np][1], b[np][2], b[np][3],
                       sb + (off ^ (((uint32_t)row & 7) << 4)));
            }
            #pragma unroll
            for (int mt = 0; mt < 2; mt++)
                #pragma unroll
                for (int np = 0; np < 2; np++) {
                    hmma(acc[mt][np*2][0],   acc[mt][np*2][1],
                         acc[mt][np*2][2],   acc[mt][np*2][3],
                         a[mt][0], a[mt][1], a[mt][2], a[mt][3],
                         b[np][0], b[np][1]);
                    hmma(acc[mt][np*2+1][0], acc[mt][np*2+1][1],
                         acc[mt][np*2+1][2], acc[mt][np*2+1][3],
                         a[mt][0], a[mt][1], a[mt][2], a[mt][3],
                         b[np][2], b[np][3]);
                }
        }
        __syncthreads();
    }

    // Epilogue: fragment (mt, nt): rows m0+wm*32+mt*16+lane/4 (+8),
    // cols n0+wn*32+nt*8+(lane&3)*2 (+1). c0,c1 adjacent cols; c2,c3 row+8.
    #pragma unroll
    for (int mt = 0; mt < 2; mt++) {
        int row = m0 + wm * 32 + mt * 16 + (lane >> 2);
        #pragma unroll
        for (int nt = 0; nt < 4; nt++) {
            int col = n0 + wn * 32 + nt * 8 + (lane & 3) * 2;
            float2 bz = *(const float2*)&bias[col];
            float x0 = fmaxf(acc[mt][nt][0] + bz.x, 0.f);
            float y0 = fmaxf(acc[mt][nt][1] + bz.y, 0.f);
            float x1 = fmaxf(acc[mt][nt][2] + bz.x, 0.f);
            float y1 = fmaxf(acc[mt][nt][3] + bz.y, 0.f);
            if (OUT_BF16) {
                __nv_bfloat16 h, l, h2, l2;
                split_bf16(x0, h, l); split_bf16(y0, h2, l2);
                ((__nv_bfloat162*)Ch)[(size_t)row * 512 + (col >> 1)] = __nv_bfloat162(h, h2);
                ((__nv_bfloat162*)Cl)[(size_t)row * 512 + (col >> 1)] = __nv_bfloat162(l, l2);
                split_bf16(x1, h, l); split_bf16(y1, h2, l2);
                ((__nv_bfloat162*)Ch)[(size_t)(row + 8) * 512 + (col >> 1)] = __nv_bfloat162(h, h2);
                ((__nv_bfloat162*)Cl)[(size_t)(row + 8) * 512 + (col >> 1)] = __nv_bfloat162(l, l2);
            } else {
                *(float2*)&Cf[(size_t)row * 1024 + col]       = make_float2(x0, y0);
                *(float2*)&Cf[(size_t)(row + 8) * 1024 + col] = make_float2(x1, y1);
            }
        }
    }
}

// ===========================================================================
// FC3: one warp per (b, o)
// ===========================================================================
__global__ __launch_bounds__(128) void fc3_kernel(
    const float* __restrict__ H2, const float* __restrict__ W3,
    const float* __restrict__ b3, float* __restrict__ out)
{
    const int b = blockIdx.x;
    const int o = threadIdx.x >> 5;
    const int l = threadIdx.x & 31;
    const float4* h = (const float4*)(H2 + b * 1024);
    const float4* w = (const float4*)(W3 + o * 1024);
    float s = 0.f;
    #pragma unroll
    for (int i = 0; i < 8; i++) {
        float4 hv = h[i * 32 + l];
        float4 wv = w[i * 32 + l];
        s = fmaf(hv.x, wv.x, s); s = fmaf(hv.y, wv.y, s);
        s = fmaf(hv.z, wv.z, s); s = fmaf(hv.w, wv.w, s);
    }
    #pragma unroll
    for (int off = 16; off; off >>= 1)
        s += __shfl_xor_sync(0xFFFFFFFFu, s, off);
    if (l == 0) out[b * 4 + o] = s + b3[o];
}

// ===========================================================================
extern "C" void kernel_launch(void* const* d_in, const int* in_sizes, int n_in,
                              void* d_out, int out_size)
{
    (void)in_sizes; (void)n_in; (void)out_size;
    const float* p1 = (const float*)d_in[0];
    const float* p2 = (const float*)d_in[1];
    const float* W1 = (const float*)d_in[2];
    const float* b1 = (const float*)d_in[3];
    const float* W2 = (const float*)d_in[4];
    const float* b2 = (const float*)d_in[5];
    const float* W3 = (const float*)d_in[6];
    const float* b3 = (const float*)d_in[7];
    float* out = (float*)d_out;

    __nv_bfloat16 *Xh, *Xl, *W1h, *W1l, *W2h, *W2l, *H1h, *H1l;
    float* H2;
    cudaGetSymbolAddress((void**)&Xh,  g_Xh);
    cudaGetSymbolAddress((void**)&Xl,  g_Xl);
    cudaGetSymbolAddress((void**)&W1h, g_W1h);
    cudaGetSymbolAddress((void**)&W1l, g_W1l);
    cudaGetSymbolAddress((void**)&W2h, g_W2h);
    cudaGetSymbolAddress((void**)&W2l, g_W2l);
    cudaGetSymbolAddress((void**)&H1h, g_H1h);
    cudaGetSymbolAddress((void**)&H1l, g_H1l);
    cudaGetSymbolAddress((void**)&H2,  g_H2);

    const int corr_smem = 2 * 49 * CORR_STRIDE * (int)sizeof(float);
    cudaFuncSetAttribute(corr_kernel,
                         cudaFuncAttributeMaxDynamicSharedMemorySize, corr_smem);
    const int gemm_smem = NS * STAGE_BYTES;   // 73728
    cudaFuncSetAttribute(hmma_fc_kernel<1>,
                         cudaFuncAttributeMaxDynamicSharedMemorySize, gemm_smem);
    cudaFuncSetAttribute(hmma_fc_kernel<0>,
                         cudaFuncAttributeMaxDynamicSharedMemorySize, gemm_smem);

    corr_kernel<<<1024, 640, corr_smem>>>(p1, p2, Xh, Xl);
    gather_w1_kernel<<<1024, 640>>>(W1, W1h, W1l);
    split_w2_kernel<<<1024, 256>>>(W2, W2h, W2l);

    dim3 grid(16, 8);   // N/64, M/128
    hmma_fc_kernel<1><<<grid, 256, gemm_smem>>>(Xh, Xl, W1h, W1l, b1,
                                                nullptr, H1h, H1l, KC_);
    hmma_fc_kernel<0><<<grid, 256, gemm_smem>>>(H1h, H1l, W2h, W2l, b2,
                                                H2, nullptr, nullptr, 1024);
    fc3_kernel<<<1024, 128>>>(H2, W3, b3, out);
}